// round 9
// baseline (speedup 1.0000x reference)
#include <cuda_runtime.h>
#include <cuda_bf16.h>
#include <cstdint>

// OctonionFanoCoherence (composition-algebra form, verified rel_err ~1.9e-6):
//   ||x̂i*x̂j - x̂k||^2 = 2 - 2*dot(omul(xi,xj), xk)*inv_i*inv_j*inv_k
//   avg_error = 2 - (2/7)*sum_l dot_l ; phi = clip(-log(avg+1e-8)*exp(ls),0,10)
//
// R9: packed f32x2 math v2 — two batch elements per thread, ALL sign handling
// via fma(neg_chain, -1, pos_chain) on the fma pipe (zero XOR/ALU ops).
// Conjugated qmul variants derived by sign substitution into the VERIFIED
// base qmul. Warp-autonomous cp.async.cg staging (R7 layout). TPB=64.

#define TPB      64
#define WARPS    (TPB / 32)
#define ELEM_F4  14                 // 14 float4 = 56 floats per element
#define WELEMS   64                 // elements per warp (2 per lane)
#define WTILE_F4 (ELEM_F4 * WELEMS) // 896 float4 = 14336 B per warp slice

typedef unsigned long long u64;
#define NEG1P 0xBF800000BF800000ULL           // packed (-1.0f, -1.0f)

__device__ __forceinline__ u64 f2mul(u64 a, u64 b) {
    u64 r; asm("mul.rn.f32x2 %0, %1, %2;" : "=l"(r) : "l"(a), "l"(b)); return r;
}
__device__ __forceinline__ u64 f2add(u64 a, u64 b) {
    u64 r; asm("add.rn.f32x2 %0, %1, %2;" : "=l"(r) : "l"(a), "l"(b)); return r;
}
__device__ __forceinline__ u64 f2fma(u64 a, u64 b, u64 c) {
    u64 r; asm("fma.rn.f32x2 %0, %1, %2, %3;" : "=l"(r) : "l"(a), "l"(b), "l"(c)); return r;
}
__device__ __forceinline__ u64 f2pack(float lo, float hi) {
    u64 r; asm("mov.b64 %0, {%1, %2};" : "=l"(r) : "f"(lo), "f"(hi)); return r;
}
__device__ __forceinline__ void f2unpack(u64 a, float& lo, float& hi) {
    asm("mov.b64 {%0, %1}, %2;" : "=f"(lo), "=f"(hi) : "l"(a));
}
// a - b on the fma pipe (avoids dependence on sub.rn.f32x2 / any XOR)
__device__ __forceinline__ u64 f2sub(u64 a, u64 b) { return f2fma(b, NEG1P, a); }

// ---- Base qmul signs (VERIFIED rounds 1/3/4):
//  r0 = p0q0 - p1q1 - p2q2 - p3q3
//  r1 = p0q1 + p1q0 + p2q3 - p3q2
//  r2 = p0q2 - p1q3 + p2q0 + p3q1
//  r3 = p0q3 + p1q2 - p2q1 + p3q0
__device__ __forceinline__ void qmul_p(const u64* p, const u64* q, u64* r) {
    u64 n, a;
    n = f2mul(p[1], q[1]); n = f2fma(p[2], q[2], n); n = f2fma(p[3], q[3], n);
    r[0] = f2fma(n, NEG1P, f2mul(p[0], q[0]));
    a = f2mul(p[0], q[1]); a = f2fma(p[1], q[0], a); a = f2fma(p[2], q[3], a);
    r[1] = f2fma(f2mul(p[3], q[2]), NEG1P, a);
    a = f2mul(p[0], q[2]); a = f2fma(p[2], q[0], a); a = f2fma(p[3], q[1], a);
    r[2] = f2fma(f2mul(p[1], q[3]), NEG1P, a);
    a = f2mul(p[0], q[3]); a = f2fma(p[1], q[2], a); a = f2fma(p[3], q[0], a);
    r[3] = f2fma(f2mul(p[2], q[1]), NEG1P, a);
}

// qmul(conj(p), q): substitute p1->-p1, p2->-p2, p3->-p3 into base:
//  r0 = p0q0 + p1q1 + p2q2 + p3q3
//  r1 = p0q1 - p1q0 - p2q3 + p3q2
//  r2 = p0q2 + p1q3 - p2q0 - p3q1
//  r3 = p0q3 - p1q2 + p2q1 - p3q0
__device__ __forceinline__ void qmul_cj1(const u64* p, const u64* q, u64* r) {
    u64 a, n;
    a = f2mul(p[0], q[0]); a = f2fma(p[1], q[1], a); a = f2fma(p[2], q[2], a);
    r[0] = f2fma(p[3], q[3], a);
    a = f2mul(p[0], q[1]); a = f2fma(p[3], q[2], a);
    n = f2mul(p[1], q[0]); n = f2fma(p[2], q[3], n);
    r[1] = f2fma(n, NEG1P, a);
    a = f2mul(p[0], q[2]); a = f2fma(p[1], q[3], a);
    n = f2mul(p[2], q[0]); n = f2fma(p[3], q[1], n);
    r[2] = f2fma(n, NEG1P, a);
    a = f2mul(p[0], q[3]); a = f2fma(p[2], q[1], a);
    n = f2mul(p[1], q[2]); n = f2fma(p[3], q[0], n);
    r[3] = f2fma(n, NEG1P, a);
}

// qmul(p, conj(q)): substitute q1->-q1, q2->-q2, q3->-q3 into base:
//  r0 = p0q0 + p1q1 + p2q2 + p3q3
//  r1 = -p0q1 + p1q0 - p2q3 + p3q2
//  r2 = -p0q2 + p1q3 + p2q0 - p3q1
//  r3 = -p0q3 - p1q2 + p2q1 + p3q0
__device__ __forceinline__ void qmul_cj2(const u64* p, const u64* q, u64* r) {
    u64 a, n;
    a = f2mul(p[0], q[0]); a = f2fma(p[1], q[1], a); a = f2fma(p[2], q[2], a);
    r[0] = f2fma(p[3], q[3], a);
    a = f2mul(p[1], q[0]); a = f2fma(p[3], q[2], a);
    n = f2mul(p[0], q[1]); n = f2fma(p[2], q[3], n);
    r[1] = f2fma(n, NEG1P, a);
    a = f2mul(p[1], q[3]); a = f2fma(p[2], q[0], a);
    n = f2mul(p[0], q[2]); n = f2fma(p[3], q[1], n);
    r[2] = f2fma(n, NEG1P, a);
    a = f2mul(p[2], q[1]); a = f2fma(p[3], q[0], a);
    n = f2mul(p[0], q[3]); n = f2fma(p[1], q[2], n);
    r[3] = f2fma(n, NEG1P, a);
}

// Packed octonion multiply, verbatim structure of verified omul:
//   z1 = qmul(a1,b1) - qmul(conj(b2), a2) ;  z2 = qmul(b2,a1) + qmul(a2, conj(b1))
__device__ __forceinline__ void omul_p(const u64* x, const u64* y, u64* z) {
    const u64* a1 = x;     const u64* a2 = x + 4;
    const u64* b1 = y;     const u64* b2 = y + 4;
    u64 t1[4], t2[4];
    qmul_p(a1, b1, t1);
    qmul_cj1(b2, a2, t2);          // == qmul(conj(b2), a2)
    z[0] = f2sub(t1[0], t2[0]); z[1] = f2sub(t1[1], t2[1]);
    z[2] = f2sub(t1[2], t2[2]); z[3] = f2sub(t1[3], t2[3]);
    qmul_p(b2, a1, t1);
    qmul_cj2(a2, b1, t2);          // == qmul(a2, conj(b1))
    z[4] = f2add(t1[0], t2[0]); z[5] = f2add(t1[1], t2[1]);
    z[6] = f2add(t1[2], t2[2]); z[7] = f2add(t1[3], t2[3]);
}

__global__ void __launch_bounds__(TPB)
oct_fano_kernel(const float* __restrict__ in,
                const float* __restrict__ log_sens,
                float* __restrict__ out,
                int B)
{
    __shared__ float4 s[WARPS][WTILE_F4];   // 2 * 14336 = 28672 B per CTA

    const int lane = threadIdx.x & 31;
    const int wid  = threadIdx.x >> 5;
    const long long warpBase =
        ((long long)blockIdx.x * WARPS + wid) * WELEMS;  // first of 64 elements

    const float esens = expf(__ldg(log_sens));

    const int elems = (int)min((long long)WELEMS, (long long)B - warpBase);
    if (elems <= 0) return;
    const int n4 = elems * ELEM_F4;

    // ---- Stage 1: warp-coalesced cp.async.cg, natural-order AoS dst ----
    const float4* src = reinterpret_cast<const float4*>(in) + warpBase * ELEM_F4;
    const uint32_t sbase = (uint32_t)__cvta_generic_to_shared(&s[wid][0]);
#pragma unroll
    for (int it = 0; it < WTILE_F4 / 32; ++it) {          // 28 iterations
        int idx4 = lane + it * 32;
        if (idx4 < n4) {
            asm volatile("cp.async.cg.shared.global [%0], [%1], 16;\n"
                         :: "r"(sbase + (uint32_t)idx4 * 16u), "l"(src + idx4)
                         : "memory");
        }
    }
    asm volatile("cp.async.commit_group;\n" ::: "memory");
    asm volatile("cp.async.wait_group 0;\n" ::: "memory");
    __syncwarp();

    // ---- Stage 2: pack elements (lane, lane+32) via scalar LDS pairs ----
    const float* fA = reinterpret_cast<const float*>(&s[wid][lane * ELEM_F4]);
    const float* fB = reinterpret_cast<const float*>(&s[wid][(lane + 32) * ELEM_F4]);
    u64 x[56];
#pragma unroll
    for (int c = 0; c < 56; ++c)
        x[c] = f2pack(fA[c], fB[c]);

    // ---- Inverse norms (rsqrt per half; == 1/max(||x||,1e-12)) ----
    u64 inv[7];
#pragma unroll
    for (int l = 0; l < 7; ++l) {
        u64 acc = f2mul(x[l*8], x[l*8]);
#pragma unroll
        for (int c = 1; c < 8; ++c)
            acc = f2fma(x[l*8 + c], x[l*8 + c], acc);
        float na, nb;
        f2unpack(acc, na, nb);
        inv[l] = f2pack(rsqrtf(fmaxf(na, 1e-24f)), rsqrtf(fmaxf(nb, 1e-24f)));
    }

    // ---- Fano lines (l, l+1 mod 7, l+3 mod 7) ----
    u64 sacc = 0;   // packed (0.0f, 0.0f)
#pragma unroll
    for (int l = 0; l < 7; ++l) {
        const int i = l, j = (l + 1) % 7, k = (l + 3) % 7;
        u64 p[8];
        omul_p(&x[i*8], &x[j*8], p);
        const u64* xk = &x[k*8];
        u64 d = f2mul(p[0], xk[0]);
#pragma unroll
        for (int c = 1; c < 8; ++c)
            d = f2fma(p[c], xk[c], d);
        u64 w = f2mul(f2mul(inv[i], inv[j]), inv[k]);
        sacc = f2fma(d, w, sacc);
    }

    // ---- Epilogue: unpack, finish scalar, coalesced stores ----
    float s0, s1;
    f2unpack(sacc, s0, s1);

    float avg0 = fmaf(s0, -2.0f / 7.0f, 2.0f);
    float phi0 = -logf(avg0 + 1e-8f) * esens;
    phi0 = fminf(fmaxf(phi0, 0.0f), 10.0f);
    if (lane < elems) out[warpBase + lane] = phi0;

    float avg1 = fmaf(s1, -2.0f / 7.0f, 2.0f);
    float phi1 = -logf(avg1 + 1e-8f) * esens;
    phi1 = fminf(fmaxf(phi1, 0.0f), 10.0f);
    if (lane + 32 < elems) out[warpBase + 32 + lane] = phi1;
}

extern "C" void kernel_launch(void* const* d_in, const int* in_sizes, int n_in,
                              void* d_out, int out_size)
{
    const float* colony   = (const float*)d_in[0];   // [B, 7, 8] fp32
    const float* log_sens = (const float*)d_in[1];   // scalar fp32
    float* out = (float*)d_out;                      // [B] fp32

    int B = in_sizes[0] / 56;
    long long per_cta = (long long)WELEMS * WARPS;   // 128 elements per CTA
    int blocks = (int)((B + per_cta - 1) / per_cta);
    oct_fano_kernel<<<blocks, TPB>>>(colony, log_sens, out, B);
}

// round 10
// speedup vs baseline: 1.5647x; 1.5647x over previous
#include <cuda_runtime.h>
#include <cuda_bf16.h>
#include <cstdint>

// OctonionFanoCoherence (composition-algebra form, verified rel_err ~1.9e-6):
//   ||x̂i*x̂j - x̂k||^2 = 2 - 2*dot(omul(xi,xj), xk)*inv_i*inv_j*inv_k
//   avg_error = 2 - (2/7)*sum_l dot_l ; phi = clip(-log(avg+1e-8)*exp(ls),0,10)
//
// R10 = R7 champion (warp-autonomous cp.async.cg staging, natural AoS smem,
// no __syncthreads) + occupancy fix (__launch_bounds__(128,8): 64-reg budget,
// 8 CTAs * 28672B smem = fits 228KB carveout -> 32 warps/SM) + MUFU log/exp
// (__logf/__expf) to shave ~30 fma-pipe ops and registers per thread.

#define TPB      128
#define WARPS    (TPB / 32)
#define ELEM_F4  14                 // 14 float4 = 56 floats per element
#define WTILE_F4 (ELEM_F4 * 32)     // 448 float4 = 7168 B per warp slice

// ---- VERIFIED rounds 1/3/4/7 — verbatim, do not re-derive ----
__device__ __forceinline__ void qmul(const float* p, const float* q, float* r) {
    r[0] = p[0]*q[0] - p[1]*q[1] - p[2]*q[2] - p[3]*q[3];
    r[1] = p[0]*q[1] + p[1]*q[0] + p[2]*q[3] - p[3]*q[2];
    r[2] = p[0]*q[2] - p[1]*q[3] + p[2]*q[0] + p[3]*q[1];
    r[3] = p[0]*q[3] + p[1]*q[2] - p[2]*q[1] + p[3]*q[0];
}
__device__ __forceinline__ void omul_v(const float* x, const float* y, float* z) {
    const float* a1 = x;     const float* a2 = x + 4;
    const float* b1 = y;     const float* b2 = y + 4;
    float t1[4], t2[4];
    qmul(a1, b1, t1);
    float cb2[4] = { b2[0], -b2[1], -b2[2], -b2[3] };
    qmul(cb2, a2, t2);
    z[0] = t1[0] - t2[0]; z[1] = t1[1] - t2[1];
    z[2] = t1[2] - t2[2]; z[3] = t1[3] - t2[3];
    qmul(b2, a1, t1);
    float cb1[4] = { b1[0], -b1[1], -b1[2], -b1[3] };
    qmul(a2, cb1, t2);
    z[4] = t1[0] + t2[0]; z[5] = t1[1] + t2[1];
    z[6] = t1[2] + t2[2]; z[7] = t1[3] + t2[3];
}
// -------------------------------------------------------------

__global__ void __launch_bounds__(TPB, 8)
oct_fano_kernel(const float* __restrict__ in,
                const float* __restrict__ log_sens,
                float* __restrict__ out,
                int B)
{
    __shared__ float4 s[WARPS][WTILE_F4];   // 4 * 7168 = 28672 B -> 8 CTAs/SM

    const int lane = threadIdx.x & 31;
    const int wid  = threadIdx.x >> 5;
    const long long warpBase =
        ((long long)blockIdx.x * WARPS + wid) * 32;   // first element of this warp

    const float esens = __expf(__ldg(log_sens));      // MUFU.EX2, overlaps loads

    const int elems = (int)min(32LL, (long long)B - warpBase);
    if (elems <= 0) return;
    const int n4 = elems * ELEM_F4;

    // ---- Stage 1: warp-coalesced cp.async.cg, natural-order AoS dst ----
    // idx4 = lane + 32*it ; dst slot = idx4 (consecutive lanes -> consecutive
    // 16B smem slots: conflict-free writes, zero index arithmetic).
    const float4* src = reinterpret_cast<const float4*>(in) + warpBase * ELEM_F4;
    const uint32_t sbase = (uint32_t)__cvta_generic_to_shared(&s[wid][0]);
#pragma unroll
    for (int it = 0; it < ELEM_F4; ++it) {
        int idx4 = lane + it * 32;
        if (idx4 < n4) {
            asm volatile("cp.async.cg.shared.global [%0], [%1], 16;\n"
                         :: "r"(sbase + (uint32_t)idx4 * 16u), "l"(src + idx4)
                         : "memory");
        }
    }
    asm volatile("cp.async.commit_group;\n" ::: "memory");
    asm volatile("cp.async.wait_group 0;\n" ::: "memory");
    __syncwarp();   // order other lanes' cp.async fills before our reads

    if (lane >= elems) return;

    // ---- Stage 2: per-thread compute (AoS read: slot = lane*14 + i) ----
    float x[56];
    const float4* buf = &s[wid][lane * ELEM_F4];
#pragma unroll
    for (int i = 0; i < ELEM_F4; ++i) {
        float4 v = buf[i];
        x[4*i + 0] = v.x; x[4*i + 1] = v.y;
        x[4*i + 2] = v.z; x[4*i + 3] = v.w;
    }

    float inv[7];
#pragma unroll
    for (int l = 0; l < 7; ++l) {
        float acc = 0.f;
#pragma unroll
        for (int c = 0; c < 8; ++c)
            acc = fmaf(x[l*8 + c], x[l*8 + c], acc);
        inv[l] = rsqrtf(fmaxf(acc, 1e-24f));   // == 1/max(||x||,1e-12)
    }

    float sacc = 0.f;
#pragma unroll
    for (int l = 0; l < 7; ++l) {
        const int i = l, j = (l + 1) % 7, k = (l + 3) % 7;
        float p[8];
        omul_v(&x[i*8], &x[j*8], p);
        const float* xk = &x[k*8];
        float d = 0.f;
#pragma unroll
        for (int c = 0; c < 8; ++c)
            d = fmaf(p[c], xk[c], d);
        sacc = fmaf(d, inv[i] * inv[j] * inv[k], sacc);
    }

    float avg = fmaf(sacc, -2.0f / 7.0f, 2.0f);    // avg_error = 2 - (2/7)*s
    float phi = -__logf(avg + 1e-8f) * esens;      // MUFU.LG2 path
    phi = fminf(fmaxf(phi, 0.0f), 10.0f);
    out[warpBase + lane] = phi;
}

extern "C" void kernel_launch(void* const* d_in, const int* in_sizes, int n_in,
                              void* d_out, int out_size)
{
    const float* colony   = (const float*)d_in[0];   // [B, 7, 8] fp32
    const float* log_sens = (const float*)d_in[1];   // scalar fp32
    float* out = (float*)d_out;                      // [B] fp32

    int B = in_sizes[0] / 56;
    long long per_cta = 32LL * WARPS;
    int blocks = (int)((B + per_cta - 1) / per_cta);
    oct_fano_kernel<<<blocks, TPB>>>(colony, log_sens, out, B);
}

// round 11
// speedup vs baseline: 1.5775x; 1.0082x over previous
#include <cuda_runtime.h>
#include <cuda_bf16.h>
#include <cstdint>

// OctonionFanoCoherence (composition-algebra form, verified rel_err ~1.7e-6):
//   ||x̂i*x̂j - x̂k||^2 = 2 - 2*dot(omul(xi,xj), xk)*inv_i*inv_j*inv_k
//   avg_error = 2 - (2/7)*sum_l dot_l ; phi = clip(-log(avg+1e-8)*exp(ls),0,10)
//
// R11: intra-warp pipelined double tile. Each warp owns 64 elements staged as
// two cp.async commit groups (A: 0-31, B: 32-63). Compute of A overlaps the
// in-flight DRAM traffic of B. Elements are processed SEQUENTIALLY per lane
// so register count stays ~64. No __syncthreads; warps are autonomous.

#define TPB      128
#define WARPS    (TPB / 32)
#define ELEM_F4  14                   // 14 float4 = 56 floats per element
#define HALF_F4  (ELEM_F4 * 32)       // 448 float4 = 7168 B per 32-elem group
#define WTILE_F4 (ELEM_F4 * 64)       // 896 float4 = 14336 B per warp slice

// ---- VERIFIED rounds 1/3/4/7/10 — verbatim, do not re-derive ----
__device__ __forceinline__ void qmul(const float* p, const float* q, float* r) {
    r[0] = p[0]*q[0] - p[1]*q[1] - p[2]*q[2] - p[3]*q[3];
    r[1] = p[0]*q[1] + p[1]*q[0] + p[2]*q[3] - p[3]*q[2];
    r[2] = p[0]*q[2] - p[1]*q[3] + p[2]*q[0] + p[3]*q[1];
    r[3] = p[0]*q[3] + p[1]*q[2] - p[2]*q[1] + p[3]*q[0];
}
__device__ __forceinline__ void omul_v(const float* x, const float* y, float* z) {
    const float* a1 = x;     const float* a2 = x + 4;
    const float* b1 = y;     const float* b2 = y + 4;
    float t1[4], t2[4];
    qmul(a1, b1, t1);
    float cb2[4] = { b2[0], -b2[1], -b2[2], -b2[3] };
    qmul(cb2, a2, t2);
    z[0] = t1[0] - t2[0]; z[1] = t1[1] - t2[1];
    z[2] = t1[2] - t2[2]; z[3] = t1[3] - t2[3];
    qmul(b2, a1, t1);
    float cb1[4] = { b1[0], -b1[1], -b1[2], -b1[3] };
    qmul(a2, cb1, t2);
    z[4] = t1[0] + t2[0]; z[5] = t1[1] + t2[1];
    z[6] = t1[2] + t2[2]; z[7] = t1[3] + t2[3];
}

// Per-element body: read 56 floats from smem (AoS slot), return phi.
__device__ __forceinline__ float oct_phi(const float4* ebase, float esens) {
    float x[56];
#pragma unroll
    for (int i = 0; i < ELEM_F4; ++i) {
        float4 v = ebase[i];
        x[4*i + 0] = v.x; x[4*i + 1] = v.y;
        x[4*i + 2] = v.z; x[4*i + 3] = v.w;
    }
    float inv[7];
#pragma unroll
    for (int l = 0; l < 7; ++l) {
        float acc = 0.f;
#pragma unroll
        for (int c = 0; c < 8; ++c)
            acc = fmaf(x[l*8 + c], x[l*8 + c], acc);
        inv[l] = rsqrtf(fmaxf(acc, 1e-24f));   // == 1/max(||x||,1e-12)
    }
    float sacc = 0.f;
#pragma unroll
    for (int l = 0; l < 7; ++l) {
        const int i = l, j = (l + 1) % 7, k = (l + 3) % 7;
        float p[8];
        omul_v(&x[i*8], &x[j*8], p);
        const float* xk = &x[k*8];
        float d = 0.f;
#pragma unroll
        for (int c = 0; c < 8; ++c)
            d = fmaf(p[c], xk[c], d);
        sacc = fmaf(d, inv[i] * inv[j] * inv[k], sacc);
    }
    float avg = fmaf(sacc, -2.0f / 7.0f, 2.0f);   // avg_error = 2 - (2/7)*s
    float phi = -__logf(avg + 1e-8f) * esens;
    return fminf(fmaxf(phi, 0.0f), 10.0f);
}
// -------------------------------------------------------------

__global__ void __launch_bounds__(TPB, 4)
oct_fano_kernel(const float* __restrict__ in,
                const float* __restrict__ log_sens,
                float* __restrict__ out,
                int B)
{
    __shared__ float4 s[WARPS][WTILE_F4];   // 4 * 14336 = 57344 B -> 4 CTAs/SM

    const int lane = threadIdx.x & 31;
    const int wid  = threadIdx.x >> 5;
    const long long warpBase =
        ((long long)blockIdx.x * WARPS + wid) * 64;   // first of 64 elements

    const float esens = __expf(__ldg(log_sens));      // MUFU, overlaps loads

    const int elems = (int)min(64LL, (long long)B - warpBase);
    if (elems <= 0) return;
    const int n4 = elems * ELEM_F4;

    const float4* src = reinterpret_cast<const float4*>(in) + warpBase * ELEM_F4;
    const uint32_t sbase = (uint32_t)__cvta_generic_to_shared(&s[wid][0]);

    // ---- Group A: elements 0..31 (float4 idx 0..447) ----
#pragma unroll
    for (int it = 0; it < ELEM_F4; ++it) {
        int idx4 = lane + it * 32;
        if (idx4 < n4) {
            asm volatile("cp.async.cg.shared.global [%0], [%1], 16;\n"
                         :: "r"(sbase + (uint32_t)idx4 * 16u), "l"(src + idx4)
                         : "memory");
        }
    }
    asm volatile("cp.async.commit_group;\n" ::: "memory");

    // ---- Group B: elements 32..63 (float4 idx 448..895) ----
#pragma unroll
    for (int it = 0; it < ELEM_F4; ++it) {
        int idx4 = HALF_F4 + lane + it * 32;
        if (idx4 < n4) {
            asm volatile("cp.async.cg.shared.global [%0], [%1], 16;\n"
                         :: "r"(sbase + (uint32_t)idx4 * 16u), "l"(src + idx4)
                         : "memory");
        }
    }
    asm volatile("cp.async.commit_group;\n" ::: "memory");

    // ---- Wait for A only (B stays in flight), compute+store A ----
    asm volatile("cp.async.wait_group 1;\n" ::: "memory");
    __syncwarp();
    if (lane < elems) {
        float phi = oct_phi(&s[wid][lane * ELEM_F4], esens);
        out[warpBase + lane] = phi;
    }

    // ---- Wait for B (mostly already arrived), compute+store B ----
    asm volatile("cp.async.wait_group 0;\n" ::: "memory");
    __syncwarp();
    if (32 + lane < elems) {
        float phi = oct_phi(&s[wid][(32 + lane) * ELEM_F4], esens);
        out[warpBase + 32 + lane] = phi;
    }
}

extern "C" void kernel_launch(void* const* d_in, const int* in_sizes, int n_in,
                              void* d_out, int out_size)
{
    const float* colony   = (const float*)d_in[0];   // [B, 7, 8] fp32
    const float* log_sens = (const float*)d_in[1];   // scalar fp32
    float* out = (float*)d_out;                      // [B] fp32

    int B = in_sizes[0] / 56;
    long long per_cta = 64LL * WARPS;                // 256 elements per CTA
    int blocks = (int)((B + per_cta - 1) / per_cta);
    oct_fano_kernel<<<blocks, TPB>>>(colony, log_sens, out, B);
}